// round 1
// baseline (speedup 1.0000x reference)
#include <cuda_runtime.h>

// Sorted segment-sum: pred_rgb[r] = sum_{s in ray r} w_s * rgb_s
// Inputs (metadata order): segment_ids int32 [N], rgb float32 [N,3],
//                          weights float32 [N,1], n_rays (unused; out_size/3)
// Strategy: HBM-bound streaming. Each thread owns CHUNK contiguous samples,
// loads them with int4/float4 (alignment guaranteed: CHUNK=16 -> 64B/64B/192B
// per-thread strides), accumulates per-segment in registers, and flushes with
// atomicAdd (compiles to RED, no return) only on segment change / chunk end.
// Expected flush count ~ N/CHUNK + N_RAYS ~ 655K * 3ch ~ 2M REDs.

static constexpr int CHUNK = 16;

__global__ void zero_out_kernel(float* __restrict__ out, int n) {
    int i = blockIdx.x * blockDim.x + threadIdx.x;
    if (i < n) out[i] = 0.0f;
}

__global__ void __launch_bounds__(256) integrate_kernel(
    const int*   __restrict__ seg,
    const float* __restrict__ rgb,
    const float* __restrict__ w,
    float*       __restrict__ out,
    int n)
{
    const long long tid  = (long long)blockIdx.x * blockDim.x + threadIdx.x;
    const long long base = tid * CHUNK;
    if (base >= n) return;

    const int cnt = (n - base >= CHUNK) ? CHUNK : (int)(n - base);

    int   sid[CHUNK];
    float wt[CHUNK];
    float rv[3 * CHUNK];

    if (cnt == CHUNK) {
        // Fully vectorized, front-batched loads (high MLP).
        const int4*   s4 = reinterpret_cast<const int4*>(seg + base);
        const float4* w4 = reinterpret_cast<const float4*>(w + base);
        const float4* r4 = reinterpret_cast<const float4*>(rgb + base * 3);
#pragma unroll
        for (int i = 0; i < CHUNK / 4; i++) {
            int4 v = s4[i];
            sid[4*i+0] = v.x; sid[4*i+1] = v.y; sid[4*i+2] = v.z; sid[4*i+3] = v.w;
        }
#pragma unroll
        for (int i = 0; i < CHUNK / 4; i++) {
            float4 v = w4[i];
            wt[4*i+0] = v.x; wt[4*i+1] = v.y; wt[4*i+2] = v.z; wt[4*i+3] = v.w;
        }
#pragma unroll
        for (int i = 0; i < (3 * CHUNK) / 4; i++) {
            float4 v = r4[i];
            rv[4*i+0] = v.x; rv[4*i+1] = v.y; rv[4*i+2] = v.z; rv[4*i+3] = v.w;
        }
    } else {
        for (int i = 0; i < cnt; i++) {
            sid[i]     = seg[base + i];
            wt[i]      = w[base + i];
            rv[3*i+0]  = rgb[(base + i) * 3 + 0];
            rv[3*i+1]  = rgb[(base + i) * 3 + 1];
            rv[3*i+2]  = rgb[(base + i) * 3 + 2];
        }
    }

    int   cur = sid[0];
    float ar = 0.0f, ag = 0.0f, ab = 0.0f;

#pragma unroll
    for (int i = 0; i < CHUNK; i++) {
        if (i >= cnt) break;
        const int s = sid[i];
        if (s != cur) {
            atomicAdd(out + 3 * cur + 0, ar);
            atomicAdd(out + 3 * cur + 1, ag);
            atomicAdd(out + 3 * cur + 2, ab);
            cur = s;
            ar = ag = ab = 0.0f;
        }
        const float ww = wt[i];
        ar = fmaf(ww, rv[3*i+0], ar);
        ag = fmaf(ww, rv[3*i+1], ag);
        ab = fmaf(ww, rv[3*i+2], ab);
    }
    atomicAdd(out + 3 * cur + 0, ar);
    atomicAdd(out + 3 * cur + 1, ag);
    atomicAdd(out + 3 * cur + 2, ab);
}

extern "C" void kernel_launch(void* const* d_in, const int* in_sizes, int n_in,
                              void* d_out, int out_size) {
    const int*   seg = (const int*)d_in[0];
    const float* rgb = (const float*)d_in[1];
    const float* w   = (const float*)d_in[2];
    float*       out = (float*)d_out;
    const int n = in_sizes[0];

    // Output is poisoned; zero it first (same stream -> ordered before atomics).
    zero_out_kernel<<<(out_size + 255) / 256, 256>>>(out, out_size);

    const long long nthreads = ((long long)n + CHUNK - 1) / CHUNK;
    const int nblocks = (int)((nthreads + 255) / 256);
    integrate_kernel<<<nblocks, 256>>>(seg, rgb, w, out, n);
}

// round 2
// speedup vs baseline: 2.3210x; 2.3210x over previous
#include <cuda_runtime.h>

// Sorted segment-sum: pred_rgb[r] = sum_{s in ray r} w_s * rgb_s
// Round 2 design:
//  - Each warp owns a tile of 128 contiguous samples; lane l owns samples
//    [tile + 4l, tile + 4l + 4). Loads: int4 (seg) + float4 (w) fully
//    coalesced; rgb = 3x float4 at 48B lane stride (3x wavefronts vs ideal,
//    acceptable: ~11us of L1 work < DRAM floor).
//  - Per-lane register accumulation over 4 samples; rare internal segment
//    boundaries flush directly via atomicAdd.
//  - Warp-level segmented SUFFIX reduction over (tail_key, tail_partial):
//    keys are sorted so equal keys are contiguous across lanes; 5 shfl.down
//    steps; only run-head lanes issue the 3 atomics. ~9 atomics / 128 samples.

__global__ void zero_out_kernel(float* __restrict__ out, int n) {
    int i = blockIdx.x * blockDim.x + threadIdx.x;
    if (i < n) out[i] = 0.0f;
}

__global__ void __launch_bounds__(256) integrate_kernel(
    const int*   __restrict__ seg,
    const float* __restrict__ rgb,
    const float* __restrict__ w,
    float*       __restrict__ out,
    int n)
{
    const int lane = threadIdx.x & 31;
    const long long warp_global =
        ((long long)blockIdx.x * blockDim.x + threadIdx.x) >> 5;
    const long long tileBase = warp_global * 128;
    if (tileBase >= n) return;            // warp-uniform exit only

    const long long base = tileBase + 4LL * lane;
    const bool valid = base < n;

    int   key;
    float ar = 0.0f, ag = 0.0f, ab = 0.0f;

    if (valid && base + 4 <= n) {
        // Vector path: coalesced-ish front-batched loads.
        const int4   s4 = *reinterpret_cast<const int4*>(seg + base);
        const float4 w4 = *reinterpret_cast<const float4*>(w + base);
        const float4* r4 = reinterpret_cast<const float4*>(rgb + base * 3);
        const float4 ra = r4[0];
        const float4 rb = r4[1];
        const float4 rc = r4[2];

        // Sample layout within the 3 float4s (AoS float3):
        //   s0: ra.x ra.y ra.z | s1: ra.w rb.x rb.y
        //   s2: rb.z rb.w rc.x | s3: rc.y rc.z rc.w
        const int   s[4] = {s4.x, s4.y, s4.z, s4.w};
        const float W[4] = {w4.x, w4.y, w4.z, w4.w};
        const float R[4] = {ra.x, ra.w, rb.z, rc.y};
        const float G[4] = {ra.y, rb.x, rb.w, rc.z};
        const float B[4] = {ra.z, rb.y, rc.x, rc.w};

        key = s[0];
#pragma unroll
        for (int i = 0; i < 4; i++) {
            if (s[i] != key) {                 // rare internal boundary
                atomicAdd(out + 3 * key + 0, ar);
                atomicAdd(out + 3 * key + 1, ag);
                atomicAdd(out + 3 * key + 2, ab);
                key = s[i];
                ar = ag = ab = 0.0f;
            }
            ar = fmaf(W[i], R[i], ar);
            ag = fmaf(W[i], G[i], ag);
            ab = fmaf(W[i], B[i], ab);
        }
    } else if (valid) {
        // Scalar tail path.
        key = seg[base];
        for (int i = 0; i < 4 && base + i < n; i++) {
            const int si = seg[base + i];
            if (si != key) {
                atomicAdd(out + 3 * key + 0, ar);
                atomicAdd(out + 3 * key + 1, ag);
                atomicAdd(out + 3 * key + 2, ab);
                key = si;
                ar = ag = ab = 0.0f;
            }
            const float ww = w[base + i];
            ar = fmaf(ww, rgb[3 * (base + i) + 0], ar);
            ag = fmaf(ww, rgb[3 * (base + i) + 1], ag);
            ab = fmaf(ww, rgb[3 * (base + i) + 2], ab);
        }
    } else {
        key = -1 - lane;   // unique sentinel: never merges, value is zero
    }

    // Segmented suffix reduction across the warp. Sorted keys => equal keys
    // are contiguous, so after log2(32) steps each run-head lane holds the
    // full run total of tail partials.
    const unsigned full = 0xffffffffu;
#pragma unroll
    for (int off = 1; off < 32; off <<= 1) {
        const int   nk = __shfl_down_sync(full, key, off);
        const float nr = __shfl_down_sync(full, ar, off);
        const float ng = __shfl_down_sync(full, ag, off);
        const float nb = __shfl_down_sync(full, ab, off);
        if (lane + off < 32 && nk == key) {
            ar += nr; ag += ng; ab += nb;
        }
    }

    const int pk = __shfl_up_sync(full, key, 1);
    const bool head = (lane == 0) || (pk != key);
    if (head && valid) {
        atomicAdd(out + 3 * key + 0, ar);
        atomicAdd(out + 3 * key + 1, ag);
        atomicAdd(out + 3 * key + 2, ab);
    }
}

extern "C" void kernel_launch(void* const* d_in, const int* in_sizes, int n_in,
                              void* d_out, int out_size) {
    const int*   seg = (const int*)d_in[0];
    const float* rgb = (const float*)d_in[1];
    const float* w   = (const float*)d_in[2];
    float*       out = (float*)d_out;
    const int n = in_sizes[0];

    zero_out_kernel<<<(out_size + 255) / 256, 256>>>(out, out_size);

    const long long nwarps  = ((long long)n + 127) / 128;
    const long long nthread = nwarps * 32;
    const int nblocks = (int)((nthread + 255) / 256);
    integrate_kernel<<<nblocks, 256>>>(seg, rgb, w, out, n);
}

// round 4
// speedup vs baseline: 2.4625x; 1.0609x over previous
#include <cuda_runtime.h>

// Sorted segment-sum: pred_rgb[r] = sum over samples s of ray r of w_s * rgb_s
// Round 4 = Round 3 resubmit (R3 bench was an infra failure, no kernel signal):
//  - cudaMemsetAsync graph memset node to zero the poisoned output (~0.3us
//    vs ~2-3us scalar kernel + launch overhead).
//  - __ldcs (streaming / evict-first) on all input loads: 169MB read-once
//    stream exceeds the 126MB L2, so resident lines are dead weight.
//  - core structure from R2 (proven 31.2us): warp tile = 128 samples, lane
//    chunk = 4 (coalesced int4/float4 for seg+w, 48B-stride float4 for rgb),
//    register accumulation, warp segmented suffix reduction, head-lane RED.

__global__ void __launch_bounds__(256) integrate_kernel(
    const int*   __restrict__ seg,
    const float* __restrict__ rgb,
    const float* __restrict__ w,
    float*       __restrict__ out,
    int n)
{
    const int lane = threadIdx.x & 31;
    const long long warp_global =
        ((long long)blockIdx.x * blockDim.x + threadIdx.x) >> 5;
    const long long tileBase = warp_global * 128;
    if (tileBase >= n) return;            // warp-uniform exit only

    const long long base = tileBase + 4LL * lane;
    const bool valid = base < n;

    int   key;
    float ar = 0.0f, ag = 0.0f, ab = 0.0f;

    if (valid && base + 4 <= n) {
        // Front-batched streaming loads (evict-first).
        const int4   s4 = __ldcs(reinterpret_cast<const int4*>(seg + base));
        const float4 w4 = __ldcs(reinterpret_cast<const float4*>(w + base));
        const float4* r4 = reinterpret_cast<const float4*>(rgb + base * 3);
        const float4 ra = __ldcs(r4 + 0);
        const float4 rb = __ldcs(r4 + 1);
        const float4 rc = __ldcs(r4 + 2);

        // AoS float3 layout within the 3 float4s:
        //   s0: ra.x ra.y ra.z | s1: ra.w rb.x rb.y
        //   s2: rb.z rb.w rc.x | s3: rc.y rc.z rc.w
        const int   s[4] = {s4.x, s4.y, s4.z, s4.w};
        const float W[4] = {w4.x, w4.y, w4.z, w4.w};
        const float R[4] = {ra.x, ra.w, rb.z, rc.y};
        const float G[4] = {ra.y, rb.x, rb.w, rc.z};
        const float B[4] = {ra.z, rb.y, rc.x, rc.w};

        key = s[0];
#pragma unroll
        for (int i = 0; i < 4; i++) {
            if (s[i] != key) {                 // rare internal boundary
                atomicAdd(out + 3 * key + 0, ar);
                atomicAdd(out + 3 * key + 1, ag);
                atomicAdd(out + 3 * key + 2, ab);
                key = s[i];
                ar = ag = ab = 0.0f;
            }
            ar = fmaf(W[i], R[i], ar);
            ag = fmaf(W[i], G[i], ag);
            ab = fmaf(W[i], B[i], ab);
        }
    } else if (valid) {
        // Scalar tail path.
        key = seg[base];
        for (int i = 0; i < 4 && base + i < n; i++) {
            const int si = seg[base + i];
            if (si != key) {
                atomicAdd(out + 3 * key + 0, ar);
                atomicAdd(out + 3 * key + 1, ag);
                atomicAdd(out + 3 * key + 2, ab);
                key = si;
                ar = ag = ab = 0.0f;
            }
            const float ww = w[base + i];
            ar = fmaf(ww, rgb[3 * (base + i) + 0], ar);
            ag = fmaf(ww, rgb[3 * (base + i) + 1], ag);
            ab = fmaf(ww, rgb[3 * (base + i) + 2], ab);
        }
    } else {
        key = -1 - lane;   // unique sentinel: never merges, value is zero
    }

    // Segmented suffix reduction across the warp (keys sorted => runs are
    // lane-contiguous; after 5 steps each run-head holds the run total).
    const unsigned full = 0xffffffffu;
#pragma unroll
    for (int off = 1; off < 32; off <<= 1) {
        const int   nk = __shfl_down_sync(full, key, off);
        const float nr = __shfl_down_sync(full, ar, off);
        const float ng = __shfl_down_sync(full, ag, off);
        const float nb = __shfl_down_sync(full, ab, off);
        if (lane + off < 32 && nk == key) {
            ar += nr; ag += ng; ab += nb;
        }
    }

    const int pk = __shfl_up_sync(full, key, 1);
    const bool head = (lane == 0) || (pk != key);
    if (head && valid) {
        atomicAdd(out + 3 * key + 0, ar);
        atomicAdd(out + 3 * key + 1, ag);
        atomicAdd(out + 3 * key + 2, ab);
    }
}

extern "C" void kernel_launch(void* const* d_in, const int* in_sizes, int n_in,
                              void* d_out, int out_size) {
    const int*   seg = (const int*)d_in[0];
    const float* rgb = (const float*)d_in[1];
    const float* w   = (const float*)d_in[2];
    float*       out = (float*)d_out;
    const int n = in_sizes[0];

    // Zero the (poisoned) output. Graph-capturable memset node; same-stream
    // ordering completes it before the atomics.
    if (out_size > 0)
        cudaMemsetAsync(out, 0, (size_t)out_size * sizeof(float));

    const long long nwarps  = ((long long)n + 127) / 128;
    const long long nthread = nwarps * 32;
    const int nblocks = (int)((nthread + 255) / 256);
    integrate_kernel<<<nblocks, 256>>>(seg, rgb, w, out, n);
}